// round 14
// baseline (speedup 1.0000x reference)
#include <cuda_runtime.h>
#include <cuda_bf16.h>

#define Hcst   1024
#define Dcst   128
#define TPcst  48
#define NBcst  384
#define Ecst   16384
#define EHcst  17408
#define OUTHALF 196608
#define MAXDEG 64
#define PBLK   51

typedef unsigned long long u64;

// ---------------- device scratch ----------------
__device__ int      g_cnt2[Hcst];         // degree counter: zero at load; k3 re-zeroes
__device__ int      g_cursor[Hcst];       // fill cursor: zeroed in kP phase A
__device__ int      g_degi[Hcst];         // copy of counts for k3
__device__ unsigned g_pkT[MAXDEG*Hcst];   // transposed edges: [e][v]
__device__ float    g_rowsum[Hcst];
__device__ float    g_S[4*Hcst];
__device__ int      g_invgrp[Hcst];
__device__ float    g_WW1[4*Dcst];
__device__ float    g_bb1[Dcst];
__device__ float    g_hpro[4*48*Dcst];
__device__ float    g_wpro[4*7*Dcst];
__device__ u64      g_barcnt;             // monotonic grid-barrier ticket

// ---------------- helpers ----------------
__device__ __forceinline__ u64 pk2(float lo, float hi) {
    u64 r; asm("mov.b64 %0,{%1,%2};" : "=l"(r) : "f"(lo), "f"(hi)); return r;
}
__device__ __forceinline__ void upk2(u64 v, float& lo, float& hi) {
    asm("mov.b64 {%0,%1},%2;" : "=f"(lo), "=f"(hi) : "l"(v));
}
__device__ __forceinline__ u64 fma2(u64 a, u64 b, u64 c) {
    u64 d; asm("fma.rn.f32x2 %0,%1,%2,%3;" : "=l"(d) : "l"(a), "l"(b), "l"(c)); return d;
}
__device__ __forceinline__ unsigned hfma2(unsigned a, unsigned b, unsigned c) {
    unsigned d; asm("fma.rn.bf16x2 %0,%1,%2,%3;" : "=r"(d) : "r"(a), "r"(b), "r"(c)); return d;
}
// relu on packed f32x2 via integer ops (negatives -> 0)
__device__ __forceinline__ u64 relu2(u64 v) {
    unsigned lo = (unsigned)v, hi = (unsigned)(v >> 32);
    lo &= ~(unsigned)((int)lo >> 31);
    hi &= ~(unsigned)((int)hi >> 31);
    return (u64)lo | ((u64)hi << 32);
}
__device__ __forceinline__ u64 pkbf4(float a, float b, float c, float d) {
    return (u64)__bfloat16_as_ushort(__float2bfloat16(a))
         | ((u64)__bfloat16_as_ushort(__float2bfloat16(b)) << 16)
         | ((u64)__bfloat16_as_ushort(__float2bfloat16(c)) << 32)
         | ((u64)__bfloat16_as_ushort(__float2bfloat16(d)) << 48);
}

// monotonic grid barrier over PBLK all-resident blocks (51 <= 148 SMs)
__device__ __forceinline__ void gridbar(int t) {
    __syncthreads();
    if (t == 0) {
        __threadfence();
        u64 my = atomicAdd(&g_barcnt, 1ULL);
        u64 target = (my/PBLK + 1) * (u64)PBLK;
        while (*(volatile u64*)&g_barcnt < target) { }
        __threadfence();
    }
    __syncthreads();
}

// ================= kP : all graph/weight prep, 51 blocks, 2 phases =================
__global__ void __launch_bounds__(512) kP(const void* ed, const void* ns,
        const float* tcw, const float* hemb, const float* wemb,
        const float* tvw, const float* tvb, const float* W1) {
    __shared__ union {
        int dummy;
        struct { float tcwS[8][516]; float embH[48][129]; float embW[7][129]; } p;
    } sm;
    __shared__ int sflag;
    int t = threadIdx.x, blk = blockIdx.x;

    // ---------- PHASE A ----------
    if (blk < 32) {
        if (t == 0) sflag = 1;
        __syncthreads();
        if (t < 64) { if (((const int*)ed)[2*t+1] != 0) atomicAnd(&sflag, 0); }
        __syncthreads();
        int i = blk*512 + t;
        int d = sflag ? (int)((const long long*)ed)[2L*i+1] : ((const int*)ed)[2*i+1];
        atomicAdd(&g_cnt2[d], 1);
    } else if (blk == 32) {
        atomicAdd(&g_cnt2[t], 1);          // self loops
        atomicAdd(&g_cnt2[t+512], 1);
        g_cursor[t] = 0; g_cursor[t+512] = 0;
    } else if (blk == 33) {
        if (t == 0) sflag = 1;
        __syncthreads();
        if (t < 64) { if (((const int*)ns)[2*t+1] != 0) atomicAnd(&sflag, 0); }
        __syncthreads();
        #pragma unroll
        for (int r = 0; r < 2; r++) {
            int i = t + r*512;
            int v = sflag ? (int)((const long long*)ns)[i] : ((const int*)ns)[i];
            g_invgrp[v] = i >> 8;
        }
    } else if (blk == 34) {
        int k = t >> 7, e = t & 127;
        float acc = 0.f;
        for (int d = 0; d < Dcst; d++) acc += tvw[d*4 + k] * W1[d*Dcst + e];
        g_WW1[k*Dcst + e] = acc;
        if (t < 128) {
            float bsum = 0.f;
            for (int d = 0; d < Dcst; d++) bsum += tvb[d] * W1[d*Dcst + t];
            g_bb1[t] = bsum;
        }
    } else if (blk == 35) {
        #pragma unroll
        for (int i = t; i < 4*Hcst; i += 512) g_S[i] = 0.f;
        #pragma unroll
        for (int i = t; i < Hcst; i += 512) g_rowsum[i] = 0.f;
    }
    gridbar(t);

    // ---------- PHASE B ----------
    if (blk < 34) {
        if (t == 0) sflag = 1;
        __syncthreads();
        if (t < 64) { if (((const int*)ed)[2*t+1] != 0) atomicAnd(&sflag, 0); }
        __syncthreads();
        int i = blk*512 + t;
        int s, d;
        if (i < Ecst) {
            if (sflag) { s = (int)((const long long*)ed)[2L*i]; d = (int)((const long long*)ed)[2L*i+1]; }
            else       { s = ((const int*)ed)[2*i];             d = ((const int*)ed)[2*i+1]; }
        } else s = d = i - Ecst;
        float w = rsqrtf((float)g_cnt2[s] * (float)g_cnt2[d]);
        int local = atomicAdd(&g_cursor[d], 1);
        unsigned cb = (unsigned)__bfloat16_as_ushort(__float2bfloat16(w));
        if (local < MAXDEG)
            g_pkT[local*Hcst + d] = (unsigned)s | (cb << 16);
        atomicAdd(&g_rowsum[d], w);
        atomicAdd(&g_S[g_invgrp[d]*Hcst + s], w * (1.f/256.f));
    } else if (blk == 50) {
        g_degi[t] = g_cnt2[t];
        g_degi[t+512] = g_cnt2[t+512];
    } else {
        // projection tables: 16 blocks (34..49), 8 d's each
        int d0 = (blk - 34)*8;
        for (int i = t; i < 8*512; i += 512)
            sm.p.tcwS[i >> 9][i & 511] = tcw[(long)(d0 + (i >> 9))*512 + (i & 511)];
        for (int i = t; i < 48*128; i += 512)
            sm.p.embH[i >> 7][i & 127] = hemb[i];
        for (int i = t; i < 7*128; i += 512)
            sm.p.embW[i >> 7][i & 127] = wemb[i];
        __syncthreads();
        int dl = t & 7;
        #pragma unroll
        for (int pass = 0; pass < 4; pass++) {
            int pair = (t >> 3) + pass*64;
            if (pair >= 220) continue;
            const float* er; float* dst; int k, r;
            if (pair < 192) { k = pair / 48; r = pair % 48; er = sm.p.embH[r]; dst = g_hpro + (k*48 + r)*Dcst; }
            else { int q = pair - 192; k = q / 7; r = q % 7; er = sm.p.embW[r]; dst = g_wpro + (k*7 + r)*Dcst; }
            float acc = 0.f;
            #pragma unroll 8
            for (int c = 0; c < 128; c++)
                acc += er[c] * sm.p.tcwS[dl][4*c + k];
            dst[d0 + dl] = acc;
        }
    }
}

// ================= k3 : per-b x-load+transpose + bf16 gather + token + epilogue =================
__global__ void __launch_bounds__(256, 3) k3(const void* xm, const float* x,
        const float* tcb, const float* b1, const float* W2, const float* b2, float* out) {
    __shared__ union { u64 Xh[Hcst]; float AccF[256][9]; } sm;   // 9.2 KB
    __shared__ __align__(16) float sY0[Hcst], sY1[Hcst], sY2[Hcst], sY3[Hcst]; // 16 KB
    __shared__ ulonglong2 sS01[512];     // 8 KB
    __shared__ ulonglong2 sS23[512];     // 8 KB
    __shared__ u64        sRSp[512];     // 4 KB
    __shared__ ulonglong2 sGM[128];      // 2 KB
    __shared__ int        sIdxH[4], sIdxW[4], sflag;

    int t = threadIdx.x, b = blockIdx.x;
    int n = b / TPcst, tp = b % TPcst;

    // block 0 resets the degree counters for the next replay
    if (b == 0) {
        #pragma unroll
        for (int r = 0; r < 4; r++) g_cnt2[t + r*256] = 0;
    }

    if (t == 0) sflag = 1;
    __syncthreads();
    if (t < 64) { if (((const int*)xm)[2*t+1] != 0) atomicAnd(&sflag, 0); }

    // prefetch packed S / rowsum into registers (committed after gather)
    u64 s0p[2], s1p[2], s2p[2], s3p[2], rsp[2];
    #pragma unroll
    for (int it = 0; it < 2; it++) {
        int vp = t + it*256;
        s0p[it] = *(const u64*)&g_S[0*Hcst + 2*vp];
        s1p[it] = *(const u64*)&g_S[1*Hcst + 2*vp];
        s2p[it] = *(const u64*)&g_S[2*Hcst + 2*vp];
        s3p[it] = *(const u64*)&g_S[3*Hcst + 2*vp];
        rsp[it] = *(const u64*)&g_rowsum[2*vp];
    }

    // ---- load x directly and transpose to bf16x4 taps in smem ----
    {
        const float4* xb = (const float4*)(x + ((long)(n*192 + tp*4))*Hcst);
        float4 r0 = xb[t], r1 = xb[256+t], r2 = xb[512+t], r3 = xb[768+t];
        u64* dst = sm.Xh + t*4;
        dst[0] = pkbf4(r0.x, r1.x, r2.x, r3.x);
        dst[1] = pkbf4(r0.y, r1.y, r2.y, r3.y);
        dst[2] = pkbf4(r0.z, r1.z, r2.z, r3.z);
        dst[3] = pkbf4(r0.w, r1.w, r2.w, r3.w);
    }
    __syncthreads();
    if (t < 8) {
        int k = t & 3, isH = t >> 2;
        long base = ((long)(n*192 + tp*4 + k))*2 + isH;
        int v = sflag ? (int)((const long long*)xm)[base] : ((const int*)xm)[base];
        if (isH) sIdxH[k] = v; else sIdxW[k] = v;
    }

    // ---- gather: bf16x2 HFMA2 accumulation, 4 v's interleaved (MLP 4) ----
    {
        int dv0 = g_degi[t], dv1 = g_degi[t+256], dv2 = g_degi[t+512], dv3 = g_degi[t+768];
        int dmax = max(max(dv0, dv1), max(dv2, dv3));
        unsigned aL0=0, aH0=0, aL1=0, aH1=0, aL2=0, aH2=0, aL3=0, aH3=0;
        for (int e = 0; e < dmax; e++) {
            const unsigned* row = g_pkT + e*Hcst + t;
            unsigned p0 = (e < dv0) ? __ldg(&row[0])   : 0u;
            unsigned p1 = (e < dv1) ? __ldg(&row[256]) : 0u;
            unsigned p2 = (e < dv2) ? __ldg(&row[512]) : 0u;
            unsigned p3 = (e < dv3) ? __ldg(&row[768]) : 0u;
            // p==0 -> w2=0 -> contributes nothing (tap 0 read harmlessly)
            #define GSTEP(p, aL, aH) { \
                u64 xv = sm.Xh[(p) & 1023u]; \
                unsigned w2 = __byte_perm((p), (p), 0x3232); \
                aL = hfma2((unsigned)xv, w2, aL); \
                aH = hfma2((unsigned)(xv >> 32), w2, aH); }
            GSTEP(p0, aL0, aH0) GSTEP(p1, aL1, aH1)
            GSTEP(p2, aL2, aH2) GSTEP(p3, aL3, aH3)
            #undef GSTEP
        }
        // convert bf16 pairs to f32 planes (token loop layout unchanged)
        #define YOUT(v, aL, aH) { \
            sY0[v] = __uint_as_float(aL << 16); \
            sY1[v] = __uint_as_float(aL & 0xFFFF0000u); \
            sY2[v] = __uint_as_float(aH << 16); \
            sY3[v] = __uint_as_float(aH & 0xFFFF0000u); }
        YOUT(t,     aL0, aH0) YOUT(t+256, aL1, aH1)
        YOUT(t+512, aL2, aH2) YOUT(t+768, aL3, aH3)
        #undef YOUT
    }
    // commit prefetched packed S / rowsum
    #pragma unroll
    for (int it = 0; it < 2; it++) {
        int vp = t + it*256;
        ulonglong2 e01, e23;
        e01.x = s0p[it]; e01.y = s1p[it];
        e23.x = s2p[it]; e23.y = s3p[it];
        sS01[vp] = e01; sS23[vp] = e23;
        sRSp[vp] = rsp[it];
    }
    __syncthreads();

    // ---- token loop ----
    int dA = t & 63, dB = dA + 64;
    int q  = t >> 6;
    u64 W0A = pk2(g_WW1[dA],     g_WW1[dA]);
    u64 W1A = pk2(g_WW1[128+dA], g_WW1[128+dA]);
    u64 W2A = pk2(g_WW1[256+dA], g_WW1[256+dA]);
    u64 W3A = pk2(g_WW1[384+dA], g_WW1[384+dA]);
    u64 BBA = pk2(g_bb1[dA],     g_bb1[dA]);
    u64 B1A = pk2(b1[dA],        b1[dA]);
    u64 W0B = pk2(g_WW1[dB],     g_WW1[dB]);
    u64 W1B = pk2(g_WW1[128+dB], g_WW1[128+dB]);
    u64 W2B = pk2(g_WW1[256+dB], g_WW1[256+dB]);
    u64 W3B = pk2(g_WW1[384+dB], g_WW1[384+dB]);
    u64 BBB = pk2(g_bb1[dB],     g_bb1[dB]);
    u64 B1B = pk2(b1[dB],        b1[dB]);
    u64 aA0 = 0, aA1 = 0, aA2 = 0, aA3 = 0;
    u64 aB0 = 0, aB1 = 0, aB2 = 0, aB3 = 0;
    int vp0 = q*128;
    #pragma unroll 2
    for (int vp = vp0; vp < vp0+128; vp++) {
        u64 yax = *(const u64*)&sY0[2*vp];
        u64 yay = *(const u64*)&sY1[2*vp];
        u64 ybx = *(const u64*)&sY2[2*vp];
        u64 yby = *(const u64*)&sY3[2*vp];
        u64 rp  = sRSp[vp];
        u64 hA = fma2(yax, W0A, B1A);
        hA = fma2(yay, W1A, hA);
        hA = fma2(ybx, W2A, hA);
        hA = fma2(yby, W3A, hA);
        hA = fma2(rp,  BBA, hA);
        u64 hB = fma2(yax, W0B, B1B);
        hB = fma2(yay, W1B, hB);
        hB = fma2(ybx, W2B, hB);
        hB = fma2(yby, W3B, hB);
        hB = fma2(rp,  BBB, hB);
        u64 hAp = relu2(hA);
        u64 hBp = relu2(hB);
        ulonglong2 s01 = sS01[vp], s23 = sS23[vp];
        aA0 = fma2(s01.x, hAp, aA0);
        aA1 = fma2(s01.y, hAp, aA1);
        aA2 = fma2(s23.x, hAp, aA2);
        aA3 = fma2(s23.y, hAp, aA3);
        aB0 = fma2(s01.x, hBp, aB0);
        aB1 = fma2(s01.y, hBp, aB1);
        aB2 = fma2(s23.x, hBp, aB2);
        aB3 = fma2(s23.y, hBp, aB3);
    }
    __syncthreads();   // Xh dead; reuse as AccF
    {
        float lo, hi;
        upk2(aA0, lo, hi); sm.AccF[t][0] = lo + hi;
        upk2(aA1, lo, hi); sm.AccF[t][1] = lo + hi;
        upk2(aA2, lo, hi); sm.AccF[t][2] = lo + hi;
        upk2(aA3, lo, hi); sm.AccF[t][3] = lo + hi;
        upk2(aB0, lo, hi); sm.AccF[t][4] = lo + hi;
        upk2(aB1, lo, hi); sm.AccF[t][5] = lo + hi;
        upk2(aB2, lo, hi); sm.AccF[t][6] = lo + hi;
        upk2(aB3, lo, hi); sm.AccF[t][7] = lo + hi;
    }
    __syncthreads();

    // ---- reduce quarters ----
    if (t < 128) {
        int d = t, lane = d & 63, useB = (d >> 6)*4;
        float g0=0.f, g1=0.f, g2=0.f, g3=0.f;
        #pragma unroll
        for (int qq = 0; qq < 4; qq++) {
            g0 += sm.AccF[qq*64+lane][useB+0];
            g1 += sm.AccF[qq*64+lane][useB+1];
            g2 += sm.AccF[qq*64+lane][useB+2];
            g3 += sm.AccF[qq*64+lane][useB+3];
        }
        ulonglong2 e;
        e.x = pk2(g0, g1); e.y = pk2(g2, g3);
        sGM[d] = e;
    }
    __syncthreads();

    // ---- epilogue: out = gm @ W2 + b2 + time ----
    if (t < 128) {
        int d = t;
        u64 o01 = 0, o23 = 0;
        #pragma unroll 4
        for (int c = 0; c < 128; c++) {
            ulonglong2 g = sGM[c];
            float w = __ldg(&W2[c*Dcst + d]);
            u64 ws = pk2(w, w);
            o01 = fma2(g.x, ws, o01);
            o23 = fma2(g.y, ws, o23);
        }
        float o0, o1, o2, o3;
        upk2(o01, o0, o1); upk2(o23, o2, o3);
        float tval = tcb[d];
        #pragma unroll
        for (int k = 0; k < 4; k++) {
            tval += g_hpro[(k*48 + sIdxH[k])*Dcst + d];
            tval += g_wpro[(k*7  + sIdxW[k])*Dcst + d];
        }
        long ob  = ((long)(n*192 + tp*4))*Dcst + d;
        long obh = OUTHALF + ob;
        out[obh] = tval; out[obh+128] = tval; out[obh+256] = tval; out[obh+384] = tval;
        float base = tval + b2[d];
        out[ob]     = o0 + base;
        out[ob+128] = o1 + base;
        out[ob+256] = o2 + base;
        out[ob+384] = o3 + base;
    }
}

// ---------------- launch ----------------
extern "C" void kernel_launch(void* const* d_in, const int* in_sizes, int n_in,
                              void* d_out, int out_size) {
    const float* x    = (const float*)d_in[0];
    const void*  xm   = d_in[1];
    const void*  ed   = d_in[2];
    const void*  ns   = d_in[3];
    const float* hemb = (const float*)d_in[4];
    const float* wemb = (const float*)d_in[5];
    const float* tcw  = (const float*)d_in[6];
    const float* tcb  = (const float*)d_in[7];
    const float* tvw  = (const float*)d_in[8];
    const float* tvb  = (const float*)d_in[9];
    const float* W1   = (const float*)d_in[10];
    const float* b1   = (const float*)d_in[11];
    const float* W2   = (const float*)d_in[12];
    const float* b2   = (const float*)d_in[13];
    float* out = (float*)d_out;

    kP<<<PBLK, 512>>>(ed, ns, tcw, hemb, wemb, tvw, tvb, W1);
    k3<<<NBcst, 256>>>(xm, x, tcb, b1, W2, b2, out);
}

// round 15
// speedup vs baseline: 1.0585x; 1.0585x over previous
#include <cuda_runtime.h>
#include <cuda_bf16.h>

#define Hcst   1024
#define Dcst   128
#define TPcst  48
#define NBcst  384
#define Ecst   16384
#define EHcst  17408
#define OUTHALF 196608
#define MAXDEG 64

typedef unsigned long long u64;

// ---------------- device scratch ----------------
__device__ int      g_cnt2[Hcst];         // degree counter: zero at load; k3 re-zeroes
__device__ int      g_cursor[Hcst];       // fill cursor: zeroed in k1
__device__ int      g_degi[Hcst];         // copy of counts for k3
__device__ unsigned g_pkT[MAXDEG*Hcst];   // transposed edges: [e][v]
__device__ float    g_rowsum[Hcst];
__device__ float    g_S[4*Hcst];
__device__ int      g_invgrp[Hcst];
__device__ float    g_WW1[4*Dcst];
__device__ float    g_bb1[Dcst];
__device__ float    g_hpro[4*48*Dcst];
__device__ float    g_wpro[4*7*Dcst];

// ---------------- helpers ----------------
__device__ __forceinline__ u64 pk2(float lo, float hi) {
    u64 r; asm("mov.b64 %0,{%1,%2};" : "=l"(r) : "f"(lo), "f"(hi)); return r;
}
__device__ __forceinline__ void upk2(u64 v, float& lo, float& hi) {
    asm("mov.b64 {%0,%1},%2;" : "=f"(lo), "=f"(hi) : "l"(v));
}
__device__ __forceinline__ u64 fma2(u64 a, u64 b, u64 c) {
    u64 d; asm("fma.rn.f32x2 %0,%1,%2,%3;" : "=l"(d) : "l"(a), "l"(b), "l"(c)); return d;
}
__device__ __forceinline__ unsigned hfma2(unsigned a, unsigned b, unsigned c) {
    unsigned d; asm("fma.rn.bf16x2 %0,%1,%2,%3;" : "=r"(d) : "r"(a), "r"(b), "r"(c)); return d;
}
// relu on packed f32x2 via integer ops (negatives -> 0)
__device__ __forceinline__ u64 relu2(u64 v) {
    unsigned lo = (unsigned)v, hi = (unsigned)(v >> 32);
    lo &= ~(unsigned)((int)lo >> 31);
    hi &= ~(unsigned)((int)hi >> 31);
    return (u64)lo | ((u64)hi << 32);
}
__device__ __forceinline__ u64 pkbf4(float a, float b, float c, float d) {
    return (u64)__bfloat16_as_ushort(__float2bfloat16(a))
         | ((u64)__bfloat16_as_ushort(__float2bfloat16(b)) << 16)
         | ((u64)__bfloat16_as_ushort(__float2bfloat16(c)) << 32)
         | ((u64)__bfloat16_as_ushort(__float2bfloat16(d)) << 48);
}

// ================= k1 : prep phase A (no transpose) =================
__global__ void __launch_bounds__(512) k1(const void* ed, const void* ns,
        const float* tvw, const float* tvb, const float* W1) {
    __shared__ int sflag;
    int t = threadIdx.x, blk = blockIdx.x;
    if (blk < 32) {
        // edge degree count: 32 x 512 edges, global atomics (distributed L2)
        if (t == 0) sflag = 1;
        __syncthreads();
        if (t < 64) { if (((const int*)ed)[2*t+1] != 0) atomicAnd(&sflag, 0); }
        __syncthreads();
        int i = blk*512 + t;
        int d = sflag ? (int)((const long long*)ed)[2L*i+1] : ((const int*)ed)[2*i+1];
        atomicAdd(&g_cnt2[d], 1);
    } else if (blk == 32) {
        atomicAdd(&g_cnt2[t], 1);          // self loops
        atomicAdd(&g_cnt2[t+512], 1);
        g_cursor[t] = 0; g_cursor[t+512] = 0;
    } else if (blk == 33) {
        if (t == 0) sflag = 1;
        __syncthreads();
        if (t < 64) { if (((const int*)ns)[2*t+1] != 0) atomicAnd(&sflag, 0); }
        __syncthreads();
        #pragma unroll
        for (int r = 0; r < 2; r++) {
            int i = t + r*512;
            int v = sflag ? (int)((const long long*)ns)[i] : ((const int*)ns)[i];
            g_invgrp[v] = i >> 8;
        }
    } else if (blk == 34) {
        int k = t >> 7, e = t & 127;
        float acc = 0.f;
        for (int d = 0; d < Dcst; d++) acc += tvw[d*4 + k] * W1[d*Dcst + e];
        g_WW1[k*Dcst + e] = acc;
        if (t < 128) {
            float bsum = 0.f;
            for (int d = 0; d < Dcst; d++) bsum += tvb[d] * W1[d*Dcst + t];
            g_bb1[t] = bsum;
        }
    } else {
        #pragma unroll
        for (int i = t; i < 4*Hcst; i += 512) g_S[i] = 0.f;
        #pragma unroll
        for (int i = t; i < Hcst; i += 512) g_rowsum[i] = 0.f;
    }
}

// ================= k2 : edge fill + projection tables + degi copy =================
__global__ void __launch_bounds__(512) k2(const void* ed,
        const float* tcw, const float* hemb, const float* wemb) {
    __shared__ union {
        int dummy;
        struct { float tcwS[8][516]; float embH[48][129]; float embW[7][129]; } p;
    } sm;
    __shared__ int sflag;
    int t = threadIdx.x, blk = blockIdx.x;
    if (blk < 34) {
        // fill pkT (+rowsum, +S): 34 x 512 = 17408
        if (t == 0) sflag = 1;
        __syncthreads();
        if (t < 64) { if (((const int*)ed)[2*t+1] != 0) atomicAnd(&sflag, 0); }
        __syncthreads();
        int i = blk*512 + t;
        int s, d;
        if (i < Ecst) {
            if (sflag) { s = (int)((const long long*)ed)[2L*i]; d = (int)((const long long*)ed)[2L*i+1]; }
            else       { s = ((const int*)ed)[2*i];             d = ((const int*)ed)[2*i+1]; }
        } else s = d = i - Ecst;
        float w = rsqrtf((float)g_cnt2[s] * (float)g_cnt2[d]);
        int local = atomicAdd(&g_cursor[d], 1);
        unsigned cb = (unsigned)__bfloat16_as_ushort(__float2bfloat16(w));
        if (local < MAXDEG)
            g_pkT[local*Hcst + d] = (unsigned)s | (cb << 16);
        atomicAdd(&g_rowsum[d], w);
        atomicAdd(&g_S[g_invgrp[d]*Hcst + s], w * (1.f/256.f));
    } else if (blk == 50) {
        g_degi[t] = g_cnt2[t];
        g_degi[t+512] = g_cnt2[t+512];
    } else {
        // projection tables: 16 blocks (34..49), 8 d's each
        int d0 = (blk - 34)*8;
        for (int i = t; i < 8*512; i += 512)
            sm.p.tcwS[i >> 9][i & 511] = tcw[(long)(d0 + (i >> 9))*512 + (i & 511)];
        for (int i = t; i < 48*128; i += 512)
            sm.p.embH[i >> 7][i & 127] = hemb[i];
        for (int i = t; i < 7*128; i += 512)
            sm.p.embW[i >> 7][i & 127] = wemb[i];
        __syncthreads();
        int dl = t & 7;
        #pragma unroll
        for (int pass = 0; pass < 4; pass++) {
            int pair = (t >> 3) + pass*64;
            if (pair >= 220) continue;
            const float* er; float* dst; int k, r;
            if (pair < 192) { k = pair / 48; r = pair % 48; er = sm.p.embH[r]; dst = g_hpro + (k*48 + r)*Dcst; }
            else { int q = pair - 192; k = q / 7; r = q % 7; er = sm.p.embW[r]; dst = g_wpro + (k*7 + r)*Dcst; }
            float acc = 0.f;
            #pragma unroll 8
            for (int c = 0; c < 128; c++)
                acc += er[c] * sm.p.tcwS[dl][4*c + k];
            dst[d0 + dl] = acc;
        }
    }
}

// ================= k3 : per-b x-load+transpose + bf16 gather + token + epilogue =================
__global__ void __launch_bounds__(256, 3) k3(const void* xm, const float* x,
        const float* tcb, const float* b1, const float* W2, const float* b2, float* out) {
    __shared__ union { u64 Xh[Hcst]; float AccF[256][9]; } sm;   // 9.2 KB
    __shared__ __align__(16) float sY0[Hcst], sY1[Hcst], sY2[Hcst], sY3[Hcst]; // 16 KB
    __shared__ ulonglong2 sS01[512];     // 8 KB
    __shared__ ulonglong2 sS23[512];     // 8 KB
    __shared__ u64        sRSp[512];     // 4 KB
    __shared__ ulonglong2 sGM[128];      // 2 KB
    __shared__ int        sIdxH[4], sIdxW[4], sflag;

    int t = threadIdx.x, b = blockIdx.x;
    int n = b / TPcst, tp = b % TPcst;

    // issue x loads FIRST (longest latency chain)
    const float4* xb = (const float4*)(x + ((long)(n*192 + tp*4))*Hcst);
    float4 r0 = xb[t], r1 = xb[256+t], r2 = xb[512+t], r3 = xb[768+t];

    // block 0 resets the degree counters for the next replay
    if (b == 0) {
        #pragma unroll
        for (int r = 0; r < 4; r++) g_cnt2[t + r*256] = 0;
    }

    if (t == 0) sflag = 1;
    __syncthreads();
    if (t < 64) { if (((const int*)xm)[2*t+1] != 0) atomicAnd(&sflag, 0); }

    // prefetch packed S / rowsum into registers (committed after gather)
    u64 s0p[2], s1p[2], s2p[2], s3p[2], rsp[2];
    #pragma unroll
    for (int it = 0; it < 2; it++) {
        int vp = t + it*256;
        s0p[it] = *(const u64*)&g_S[0*Hcst + 2*vp];
        s1p[it] = *(const u64*)&g_S[1*Hcst + 2*vp];
        s2p[it] = *(const u64*)&g_S[2*Hcst + 2*vp];
        s3p[it] = *(const u64*)&g_S[3*Hcst + 2*vp];
        rsp[it] = *(const u64*)&g_rowsum[2*vp];
    }

    // ---- transpose x to bf16x4 taps in smem ----
    {
        u64* dst = sm.Xh + t*4;
        dst[0] = pkbf4(r0.x, r1.x, r2.x, r3.x);
        dst[1] = pkbf4(r0.y, r1.y, r2.y, r3.y);
        dst[2] = pkbf4(r0.z, r1.z, r2.z, r3.z);
        dst[3] = pkbf4(r0.w, r1.w, r2.w, r3.w);
    }
    __syncthreads();
    if (t < 8) {
        int k = t & 3, isH = t >> 2;
        long base = ((long)(n*192 + tp*4 + k))*2 + isH;
        int v = sflag ? (int)((const long long*)xm)[base] : ((const int*)xm)[base];
        if (isH) sIdxH[k] = v; else sIdxW[k] = v;
    }

    // ---- gather: bf16x2 HFMA2 accumulation, 4 v's interleaved (MLP 4) ----
    {
        int dv0 = g_degi[t], dv1 = g_degi[t+256], dv2 = g_degi[t+512], dv3 = g_degi[t+768];
        int dmax = max(max(dv0, dv1), max(dv2, dv3));
        unsigned aL0=0, aH0=0, aL1=0, aH1=0, aL2=0, aH2=0, aL3=0, aH3=0;
        for (int e = 0; e < dmax; e++) {
            const unsigned* row = g_pkT + e*Hcst + t;
            unsigned p0 = (e < dv0) ? __ldg(&row[0])   : 0u;
            unsigned p1 = (e < dv1) ? __ldg(&row[256]) : 0u;
            unsigned p2 = (e < dv2) ? __ldg(&row[512]) : 0u;
            unsigned p3 = (e < dv3) ? __ldg(&row[768]) : 0u;
            // p==0 -> w2=0 -> contributes nothing (tap 0 read harmlessly)
            #define GSTEP(p, aL, aH) { \
                u64 xv = sm.Xh[(p) & 1023u]; \
                unsigned w2 = __byte_perm((p), (p), 0x3232); \
                aL = hfma2((unsigned)xv, w2, aL); \
                aH = hfma2((unsigned)(xv >> 32), w2, aH); }
            GSTEP(p0, aL0, aH0) GSTEP(p1, aL1, aH1)
            GSTEP(p2, aL2, aH2) GSTEP(p3, aL3, aH3)
            #undef GSTEP
        }
        // convert bf16 pairs to f32 planes (token loop layout unchanged)
        #define YOUT(v, aL, aH) { \
            sY0[v] = __uint_as_float(aL << 16); \
            sY1[v] = __uint_as_float(aL & 0xFFFF0000u); \
            sY2[v] = __uint_as_float(aH << 16); \
            sY3[v] = __uint_as_float(aH & 0xFFFF0000u); }
        YOUT(t,     aL0, aH0) YOUT(t+256, aL1, aH1)
        YOUT(t+512, aL2, aH2) YOUT(t+768, aL3, aH3)
        #undef YOUT
    }
    // commit prefetched packed S / rowsum
    #pragma unroll
    for (int it = 0; it < 2; it++) {
        int vp = t + it*256;
        ulonglong2 e01, e23;
        e01.x = s0p[it]; e01.y = s1p[it];
        e23.x = s2p[it]; e23.y = s3p[it];
        sS01[vp] = e01; sS23[vp] = e23;
        sRSp[vp] = rsp[it];
    }
    __syncthreads();

    // ---- token loop ----
    int dA = t & 63, dB = dA + 64;
    int q  = t >> 6;
    u64 W0A = pk2(g_WW1[dA],     g_WW1[dA]);
    u64 W1A = pk2(g_WW1[128+dA], g_WW1[128+dA]);
    u64 W2A = pk2(g_WW1[256+dA], g_WW1[256+dA]);
    u64 W3A = pk2(g_WW1[384+dA], g_WW1[384+dA]);
    u64 BBA = pk2(g_bb1[dA],     g_bb1[dA]);
    u64 B1A = pk2(b1[dA],        b1[dA]);
    u64 W0B = pk2(g_WW1[dB],     g_WW1[dB]);
    u64 W1B = pk2(g_WW1[128+dB], g_WW1[128+dB]);
    u64 W2B = pk2(g_WW1[256+dB], g_WW1[256+dB]);
    u64 W3B = pk2(g_WW1[384+dB], g_WW1[384+dB]);
    u64 BBB = pk2(g_bb1[dB],     g_bb1[dB]);
    u64 B1B = pk2(b1[dB],        b1[dB]);
    u64 aA0 = 0, aA1 = 0, aA2 = 0, aA3 = 0;
    u64 aB0 = 0, aB1 = 0, aB2 = 0, aB3 = 0;
    int vp0 = q*128;
    #pragma unroll 2
    for (int vp = vp0; vp < vp0+128; vp++) {
        u64 yax = *(const u64*)&sY0[2*vp];
        u64 yay = *(const u64*)&sY1[2*vp];
        u64 ybx = *(const u64*)&sY2[2*vp];
        u64 yby = *(const u64*)&sY3[2*vp];
        u64 rp  = sRSp[vp];
        u64 hA = fma2(yax, W0A, B1A);
        hA = fma2(yay, W1A, hA);
        hA = fma2(ybx, W2A, hA);
        hA = fma2(yby, W3A, hA);
        hA = fma2(rp,  BBA, hA);
        u64 hB = fma2(yax, W0B, B1B);
        hB = fma2(yay, W1B, hB);
        hB = fma2(ybx, W2B, hB);
        hB = fma2(yby, W3B, hB);
        hB = fma2(rp,  BBB, hB);
        u64 hAp = relu2(hA);
        u64 hBp = relu2(hB);
        ulonglong2 s01 = sS01[vp], s23 = sS23[vp];
        aA0 = fma2(s01.x, hAp, aA0);
        aA1 = fma2(s01.y, hAp, aA1);
        aA2 = fma2(s23.x, hAp, aA2);
        aA3 = fma2(s23.y, hAp, aA3);
        aB0 = fma2(s01.x, hBp, aB0);
        aB1 = fma2(s01.y, hBp, aB1);
        aB2 = fma2(s23.x, hBp, aB2);
        aB3 = fma2(s23.y, hBp, aB3);
    }
    __syncthreads();   // Xh dead; reuse as AccF
    {
        float lo, hi;
        upk2(aA0, lo, hi); sm.AccF[t][0] = lo + hi;
        upk2(aA1, lo, hi); sm.AccF[t][1] = lo + hi;
        upk2(aA2, lo, hi); sm.AccF[t][2] = lo + hi;
        upk2(aA3, lo, hi); sm.AccF[t][3] = lo + hi;
        upk2(aB0, lo, hi); sm.AccF[t][4] = lo + hi;
        upk2(aB1, lo, hi); sm.AccF[t][5] = lo + hi;
        upk2(aB2, lo, hi); sm.AccF[t][6] = lo + hi;
        upk2(aB3, lo, hi); sm.AccF[t][7] = lo + hi;
    }
    __syncthreads();

    // ---- reduce quarters ----
    if (t < 128) {
        int d = t, lane = d & 63, useB = (d >> 6)*4;
        float g0=0.f, g1=0.f, g2=0.f, g3=0.f;
        #pragma unroll
        for (int qq = 0; qq < 4; qq++) {
            g0 += sm.AccF[qq*64+lane][useB+0];
            g1 += sm.AccF[qq*64+lane][useB+1];
            g2 += sm.AccF[qq*64+lane][useB+2];
            g3 += sm.AccF[qq*64+lane][useB+3];
        }
        ulonglong2 e;
        e.x = pk2(g0, g1); e.y = pk2(g2, g3);
        sGM[d] = e;
    }
    __syncthreads();

    // ---- epilogue: out = gm @ W2 + b2 + time ----
    if (t < 128) {
        int d = t;
        u64 o01 = 0, o23 = 0;
        #pragma unroll 4
        for (int c = 0; c < 128; c++) {
            ulonglong2 g = sGM[c];
            float w = __ldg(&W2[c*Dcst + d]);
            u64 ws = pk2(w, w);
            o01 = fma2(g.x, ws, o01);
            o23 = fma2(g.y, ws, o23);
        }
        float o0, o1, o2, o3;
        upk2(o01, o0, o1); upk2(o23, o2, o3);
        float tval = tcb[d];
        #pragma unroll
        for (int k = 0; k < 4; k++) {
            tval += g_hpro[(k*48 + sIdxH[k])*Dcst + d];
            tval += g_wpro[(k*7  + sIdxW[k])*Dcst + d];
        }
        long ob  = ((long)(n*192 + tp*4))*Dcst + d;
        long obh = OUTHALF + ob;
        out[obh] = tval; out[obh+128] = tval; out[obh+256] = tval; out[obh+384] = tval;
        float base = tval + b2[d];
        out[ob]     = o0 + base;
        out[ob+128] = o1 + base;
        out[ob+256] = o2 + base;
        out[ob+384] = o3 + base;
    }
}

// ---------------- launch ----------------
extern "C" void kernel_launch(void* const* d_in, const int* in_sizes, int n_in,
                              void* d_out, int out_size) {
    const float* x    = (const float*)d_in[0];
    const void*  xm   = d_in[1];
    const void*  ed   = d_in[2];
    const void*  ns   = d_in[3];
    const float* hemb = (const float*)d_in[4];
    const float* wemb = (const float*)d_in[5];
    const float* tcw  = (const float*)d_in[6];
    const float* tcb  = (const float*)d_in[7];
    const float* tvw  = (const float*)d_in[8];
    const float* tvb  = (const float*)d_in[9];
    const float* W1   = (const float*)d_in[10];
    const float* b1   = (const float*)d_in[11];
    const float* W2   = (const float*)d_in[12];
    const float* b2   = (const float*)d_in[13];
    float* out = (float*)d_out;

    k1<<<36, 512>>>(ed, ns, tvw, tvb, W1);
    k2<<<51, 512>>>(ed, tcw, hemb, wemb);
    k3<<<NBcst, 256>>>(xm, x, tcb, b1, W2, b2, out);
}

// round 16
// speedup vs baseline: 1.1352x; 1.0725x over previous
#include <cuda_runtime.h>
#include <cuda_bf16.h>

#define Hcst   1024
#define Dcst   128
#define TPcst  48
#define NBcst  384
#define Ecst   16384
#define EHcst  17408
#define OUTHALF 196608
#define MAXDEG 64

typedef unsigned long long u64;

// ---------------- device scratch ----------------
__device__ int      g_cnt2[Hcst];         // degree counter: zero at load; k3 re-zeroes
__device__ int      g_cursor[Hcst];       // fill cursor: zeroed in k1
__device__ unsigned g_pkT[MAXDEG*Hcst];   // transposed edges [e][v]; zero-padded by k1
__device__ int      g_dmax;               // block-uniform gather trip count (k2)
__device__ float    g_rowsum[Hcst];
__device__ float    g_S[4*Hcst];
__device__ int      g_invgrp[Hcst];
__device__ float    g_WW1[4*Dcst];
__device__ float    g_bb1[Dcst];
__device__ float    g_hpro[4*48*Dcst];
__device__ float    g_wpro[4*7*Dcst];

// ---------------- helpers ----------------
__device__ __forceinline__ u64 pk2(float lo, float hi) {
    u64 r; asm("mov.b64 %0,{%1,%2};" : "=l"(r) : "f"(lo), "f"(hi)); return r;
}
__device__ __forceinline__ void upk2(u64 v, float& lo, float& hi) {
    asm("mov.b64 {%0,%1},%2;" : "=f"(lo), "=f"(hi) : "l"(v));
}
__device__ __forceinline__ u64 fma2(u64 a, u64 b, u64 c) {
    u64 d; asm("fma.rn.f32x2 %0,%1,%2,%3;" : "=l"(d) : "l"(a), "l"(b), "l"(c)); return d;
}
__device__ __forceinline__ u64 add2(u64 a, u64 b) {
    u64 d; asm("add.rn.f32x2 %0,%1,%2;" : "=l"(d) : "l"(a), "l"(b)); return d;
}
__device__ __forceinline__ unsigned hfma2(unsigned a, unsigned b, unsigned c) {
    unsigned d; asm("fma.rn.bf16x2 %0,%1,%2,%3;" : "=r"(d) : "r"(a), "r"(b), "r"(c)); return d;
}
// relu on packed f32x2 via integer ops (negatives -> 0)
__device__ __forceinline__ u64 relu2(u64 v) {
    unsigned lo = (unsigned)v, hi = (unsigned)(v >> 32);
    lo &= ~(unsigned)((int)lo >> 31);
    hi &= ~(unsigned)((int)hi >> 31);
    return (u64)lo | ((u64)hi << 32);
}
__device__ __forceinline__ u64 pkbf4(float a, float b, float c, float d) {
    return (u64)__bfloat16_as_ushort(__float2bfloat16(a))
         | ((u64)__bfloat16_as_ushort(__float2bfloat16(b)) << 16)
         | ((u64)__bfloat16_as_ushort(__float2bfloat16(c)) << 32)
         | ((u64)__bfloat16_as_ushort(__float2bfloat16(d)) << 48);
}

// ================= k1 : everything dependency-free (rides the first-launch ramp) =================
__global__ void __launch_bounds__(512) k1(const void* ed, const void* ns,
        const float* tcw, const float* hemb, const float* wemb,
        const float* tvw, const float* tvb, const float* W1) {
    __shared__ union {
        int dummy;
        struct { float tcwS[8][516]; float embH[48][129]; float embW[7][129]; } p;
    } sm;
    __shared__ int sflag;
    int t = threadIdx.x, blk = blockIdx.x;
    if (blk < 32) {
        // edge degree count: 32 x 512 edges, global atomics (distributed L2)
        if (t == 0) sflag = 1;
        __syncthreads();
        if (t < 64) { if (((const int*)ed)[2*t+1] != 0) atomicAnd(&sflag, 0); }
        __syncthreads();
        int i = blk*512 + t;
        int d = sflag ? (int)((const long long*)ed)[2L*i+1] : ((const int*)ed)[2*i+1];
        atomicAdd(&g_cnt2[d], 1);
    } else if (blk == 32) {
        atomicAdd(&g_cnt2[t], 1);          // self loops
        atomicAdd(&g_cnt2[t+512], 1);
        g_cursor[t] = 0; g_cursor[t+512] = 0;
    } else if (blk == 33) {
        if (t == 0) sflag = 1;
        __syncthreads();
        if (t < 64) { if (((const int*)ns)[2*t+1] != 0) atomicAnd(&sflag, 0); }
        __syncthreads();
        #pragma unroll
        for (int r = 0; r < 2; r++) {
            int i = t + r*512;
            int v = sflag ? (int)((const long long*)ns)[i] : ((const int*)ns)[i];
            g_invgrp[v] = i >> 8;
        }
    } else if (blk == 34) {
        int k = t >> 7, e = t & 127;
        float acc = 0.f;
        for (int d = 0; d < Dcst; d++) acc += tvw[d*4 + k] * W1[d*Dcst + e];
        g_WW1[k*Dcst + e] = acc;
        if (t < 128) {
            float bsum = 0.f;
            for (int d = 0; d < Dcst; d++) bsum += tvb[d] * W1[d*Dcst + t];
            g_bb1[t] = bsum;
        }
    } else if (blk == 35) {
        #pragma unroll
        for (int i = t; i < 4*Hcst; i += 512) g_S[i] = 0.f;
        #pragma unroll
        for (int i = t; i < Hcst; i += 512) g_rowsum[i] = 0.f;
    } else if (blk < 44) {
        // zero pkT: 8 blocks x 32KB (rows beyond degree stay coef=0)
        u64* p = (u64*)g_pkT + (blk-36)*4096;
        #pragma unroll
        for (int r = 0; r < 8; r++) p[t + r*512] = 0ULL;
    } else {
        // projection tables: 16 blocks (44..59), 8 d's each
        int d0 = (blk - 44)*8;
        for (int i = t; i < 8*512; i += 512)
            sm.p.tcwS[i >> 9][i & 511] = tcw[(long)(d0 + (i >> 9))*512 + (i & 511)];
        for (int i = t; i < 48*128; i += 512)
            sm.p.embH[i >> 7][i & 127] = hemb[i];
        for (int i = t; i < 7*128; i += 512)
            sm.p.embW[i >> 7][i & 127] = wemb[i];
        __syncthreads();
        int dl = t & 7;
        #pragma unroll
        for (int pass = 0; pass < 4; pass++) {
            int pair = (t >> 3) + pass*64;
            if (pair >= 220) continue;
            const float* er; float* dst; int k, r;
            if (pair < 192) { k = pair / 48; r = pair % 48; er = sm.p.embH[r]; dst = g_hpro + (k*48 + r)*Dcst; }
            else { int q = pair - 192; k = q / 7; r = q % 7; er = sm.p.embW[r]; dst = g_wpro + (k*7 + r)*Dcst; }
            float acc = 0.f;
            #pragma unroll 8
            for (int c = 0; c < 128; c++)
                acc += er[c] * sm.p.tcwS[dl][4*c + k];
            dst[d0 + dl] = acc;
        }
    }
}

// ================= k2 : edge fill + dmax =================
__global__ void __launch_bounds__(512) k2(const void* ed) {
    __shared__ int sflag;
    int t = threadIdx.x, blk = blockIdx.x;
    if (blk < 34) {
        // fill pkT (+rowsum, +S): 34 x 512 = 17408
        if (t == 0) sflag = 1;
        __syncthreads();
        if (t < 64) { if (((const int*)ed)[2*t+1] != 0) atomicAnd(&sflag, 0); }
        __syncthreads();
        int i = blk*512 + t;
        int s, d;
        if (i < Ecst) {
            if (sflag) { s = (int)((const long long*)ed)[2L*i]; d = (int)((const long long*)ed)[2L*i+1]; }
            else       { s = ((const int*)ed)[2*i];             d = ((const int*)ed)[2*i+1]; }
        } else s = d = i - Ecst;
        float w = rsqrtf((float)g_cnt2[s] * (float)g_cnt2[d]);
        int local = atomicAdd(&g_cursor[d], 1);
        unsigned cb = (unsigned)__bfloat16_as_ushort(__float2bfloat16(w));
        if (local < MAXDEG)
            g_pkT[local*Hcst + d] = (unsigned)s | (cb << 16);
        atomicAdd(&g_rowsum[d], w);
        atomicAdd(&g_S[g_invgrp[d]*Hcst + s], w * (1.f/256.f));
    } else {
        // block-uniform gather trip count: max degree, clamped, rounded even
        __shared__ int red[16];
        int lane = t & 31, wid = t >> 5;
        int m = max(g_cnt2[t], g_cnt2[t+512]);
        #pragma unroll
        for (int o = 16; o >= 1; o >>= 1) m = max(m, __shfl_xor_sync(~0u, m, o));
        if (lane == 0) red[wid] = m;
        __syncthreads();
        if (wid == 0) {
            m = (lane < 16) ? red[lane] : 0;
            #pragma unroll
            for (int o = 8; o >= 1; o >>= 1) m = max(m, __shfl_xor_sync(~0u, m, o));
            if (lane == 0) {
                m = min(m, MAXDEG);
                g_dmax = (m + 1) & ~1;     // even for unroll-2
            }
        }
    }
}

// ================= k3 : per-b x-load+transpose + branch-free gather + token + epilogue =================
__global__ void __launch_bounds__(256, 3) k3(const void* xm, const float* x,
        const float* tcb, const float* b1, const float* W2, const float* b2, float* out) {
    __shared__ union {
        u64 Xh[Hcst];                      // 8 KB (gather taps)
        union { float AccF[256][9]; u64 epi[256][2]; } r;   // 9.2 KB
    } sm;
    __shared__ __align__(16) float sYI[512*8];   // 16 KB interleaved Y
    __shared__ ulonglong2 sS01[512];     // 8 KB
    __shared__ ulonglong2 sS23[512];     // 8 KB
    __shared__ u64        sRSp[512];     // 4 KB
    __shared__ ulonglong2 sGM[128];      // 2 KB
    __shared__ int        sIdxH[4], sIdxW[4], sflag;

    int t = threadIdx.x, b = blockIdx.x;
    int n = b / TPcst, tp = b % TPcst;

    // issue x loads FIRST (longest latency chain)
    const float4* xb = (const float4*)(x + ((long)(n*192 + tp*4))*Hcst);
    float4 r0 = xb[t], r1 = xb[256+t], r2 = xb[512+t], r3 = xb[768+t];

    // block 0 resets the degree counters for the next replay
    if (b == 0) {
        #pragma unroll
        for (int r = 0; r < 4; r++) g_cnt2[t + r*256] = 0;
    }

    if (t == 0) sflag = 1;
    __syncthreads();
    if (t < 64) { if (((const int*)xm)[2*t+1] != 0) atomicAnd(&sflag, 0); }

    // prefetch packed S / rowsum into registers (committed after gather)
    u64 s0p[2], s1p[2], s2p[2], s3p[2], rsp[2];
    #pragma unroll
    for (int it = 0; it < 2; it++) {
        int vp = t + it*256;
        s0p[it] = *(const u64*)&g_S[0*Hcst + 2*vp];
        s1p[it] = *(const u64*)&g_S[1*Hcst + 2*vp];
        s2p[it] = *(const u64*)&g_S[2*Hcst + 2*vp];
        s3p[it] = *(const u64*)&g_S[3*Hcst + 2*vp];
        rsp[it] = *(const u64*)&g_rowsum[2*vp];
    }

    // ---- transpose x to bf16x4 taps in smem ----
    {
        u64* dst = sm.Xh + t*4;
        dst[0] = pkbf4(r0.x, r1.x, r2.x, r3.x);
        dst[1] = pkbf4(r0.y, r1.y, r2.y, r3.y);
        dst[2] = pkbf4(r0.z, r1.z, r2.z, r3.z);
        dst[3] = pkbf4(r0.w, r1.w, r2.w, r3.w);
    }
    __syncthreads();
    if (t < 8) {
        int k = t & 3, isH = t >> 2;
        long base = ((long)(n*192 + tp*4 + k))*2 + isH;
        int v = sflag ? (int)((const long long*)xm)[base] : ((const int*)xm)[base];
        if (isH) sIdxH[k] = v; else sIdxW[k] = v;
    }

    // ---- gather: branch-free (zero-padded pkT), bf16 HFMA2, 4 v's interleaved ----
    {
        int dmax = g_dmax;   // even, uniform across block
        unsigned aL0=0, aH0=0, aL1=0, aH1=0, aL2=0, aH2=0, aL3=0, aH3=0;
        #pragma unroll 2
        for (int e = 0; e < dmax; e++) {
            const unsigned* row = g_pkT + e*Hcst + t;
            unsigned p0 = __ldg(&row[0]);
            unsigned p1 = __ldg(&row[256]);
            unsigned p2 = __ldg(&row[512]);
            unsigned p3 = __ldg(&row[768]);
            // p==0 -> w2=0 -> contributes nothing
            #define GSTEP(p, aL, aH) { \
                u64 xv = sm.Xh[(p) & 1023u]; \
                unsigned w2 = __byte_perm((p), (p), 0x3232); \
                aL = hfma2((unsigned)xv, w2, aL); \
                aH = hfma2((unsigned)(xv >> 32), w2, aH); }
            GSTEP(p0, aL0, aH0) GSTEP(p1, aL1, aH1)
            GSTEP(p2, aL2, aH2) GSTEP(p3, aL3, aH3)
            #undef GSTEP
        }
        // write interleaved f32 planes: sYI[(v>>1)*8 + plane*2 + (v&1)]
        #define YOUT(v, aL, aH) { \
            int base = ((v) >> 1)*8 + ((v) & 1); \
            sYI[base + 0] = __uint_as_float(aL << 16); \
            sYI[base + 2] = __uint_as_float(aL & 0xFFFF0000u); \
            sYI[base + 4] = __uint_as_float(aH << 16); \
            sYI[base + 6] = __uint_as_float(aH & 0xFFFF0000u); }
        YOUT(t,     aL0, aH0) YOUT(t+256, aL1, aH1)
        YOUT(t+512, aL2, aH2) YOUT(t+768, aL3, aH3)
        #undef YOUT
    }
    // commit prefetched packed S / rowsum
    #pragma unroll
    for (int it = 0; it < 2; it++) {
        int vp = t + it*256;
        ulonglong2 e01, e23;
        e01.x = s0p[it]; e01.y = s1p[it];
        e23.x = s2p[it]; e23.y = s3p[it];
        sS01[vp] = e01; sS23[vp] = e23;
        sRSp[vp] = rsp[it];
    }
    __syncthreads();

    // ---- token loop ----
    int dA = t & 63, dB = dA + 64;
    int q  = t >> 6;
    u64 W0A = pk2(g_WW1[dA],     g_WW1[dA]);
    u64 W1A = pk2(g_WW1[128+dA], g_WW1[128+dA]);
    u64 W2A = pk2(g_WW1[256+dA], g_WW1[256+dA]);
    u64 W3A = pk2(g_WW1[384+dA], g_WW1[384+dA]);
    u64 BBA = pk2(g_bb1[dA],     g_bb1[dA]);
    u64 B1A = pk2(b1[dA],        b1[dA]);
    u64 W0B = pk2(g_WW1[dB],     g_WW1[dB]);
    u64 W1B = pk2(g_WW1[128+dB], g_WW1[128+dB]);
    u64 W2B = pk2(g_WW1[256+dB], g_WW1[256+dB]);
    u64 W3B = pk2(g_WW1[384+dB], g_WW1[384+dB]);
    u64 BBB = pk2(g_bb1[dB],     g_bb1[dB]);
    u64 B1B = pk2(b1[dB],        b1[dB]);
    u64 aA0 = 0, aA1 = 0, aA2 = 0, aA3 = 0;
    u64 aB0 = 0, aB1 = 0, aB2 = 0, aB3 = 0;
    int vp0 = q*128;
    #pragma unroll 2
    for (int vp = vp0; vp < vp0+128; vp++) {
        const ulonglong2* yp = (const ulonglong2*)&sYI[vp*8];
        ulonglong2 la = yp[0], lb = yp[1];
        u64 rp  = sRSp[vp];
        u64 hA = fma2(la.x, W0A, B1A);
        hA = fma2(la.y, W1A, hA);
        hA = fma2(lb.x, W2A, hA);
        hA = fma2(lb.y, W3A, hA);
        hA = fma2(rp,  BBA, hA);
        u64 hB = fma2(la.x, W0B, B1B);
        hB = fma2(la.y, W1B, hB);
        hB = fma2(lb.x, W2B, hB);
        hB = fma2(lb.y, W3B, hB);
        hB = fma2(rp,  BBB, hB);
        u64 hAp = relu2(hA);
        u64 hBp = relu2(hB);
        ulonglong2 s01 = sS01[vp], s23 = sS23[vp];
        aA0 = fma2(s01.x, hAp, aA0);
        aA1 = fma2(s01.y, hAp, aA1);
        aA2 = fma2(s23.x, hAp, aA2);
        aA3 = fma2(s23.y, hAp, aA3);
        aB0 = fma2(s01.x, hBp, aB0);
        aB1 = fma2(s01.y, hBp, aB1);
        aB2 = fma2(s23.x, hBp, aB2);
        aB3 = fma2(s23.y, hBp, aB3);
    }
    __syncthreads();   // Xh dead; reuse as AccF
    {
        float lo, hi;
        upk2(aA0, lo, hi); sm.r.AccF[t][0] = lo + hi;
        upk2(aA1, lo, hi); sm.r.AccF[t][1] = lo + hi;
        upk2(aA2, lo, hi); sm.r.AccF[t][2] = lo + hi;
        upk2(aA3, lo, hi); sm.r.AccF[t][3] = lo + hi;
        upk2(aB0, lo, hi); sm.r.AccF[t][4] = lo + hi;
        upk2(aB1, lo, hi); sm.r.AccF[t][5] = lo + hi;
        upk2(aB2, lo, hi); sm.r.AccF[t][6] = lo + hi;
        upk2(aB3, lo, hi); sm.r.AccF[t][7] = lo + hi;
    }
    __syncthreads();

    // ---- reduce quarters ----
    if (t < 128) {
        int d = t, lane = d & 63, useB = (d >> 6)*4;
        float g0=0.f, g1=0.f, g2=0.f, g3=0.f;
        #pragma unroll
        for (int qq = 0; qq < 4; qq++) {
            g0 += sm.r.AccF[qq*64+lane][useB+0];
            g1 += sm.r.AccF[qq*64+lane][useB+1];
            g2 += sm.r.AccF[qq*64+lane][useB+2];
            g3 += sm.r.AccF[qq*64+lane][useB+3];
        }
        ulonglong2 e;
        e.x = pk2(g0, g1); e.y = pk2(g2, g3);
        sGM[d] = e;
    }
    __syncthreads();

    // ---- epilogue: W2 dot split across all 256 threads ----
    {
        int d = t & 127, half = t >> 7;
        u64 o01 = 0, o23 = 0;
        int c0 = half*64;
        #pragma unroll 4
        for (int c = c0; c < c0+64; c++) {
            ulonglong2 g = sGM[c];
            float w = __ldg(&W2[c*Dcst + d]);
            u64 ws = pk2(w, w);
            o01 = fma2(g.x, ws, o01);
            o23 = fma2(g.y, ws, o23);
        }
        __syncthreads();   // AccF reads done; overlay epi
        sm.r.epi[t][0] = o01;
        sm.r.epi[t][1] = o23;
    }
    __syncthreads();

    if (t < 128) {
        int d = t;
        u64 o01 = add2(sm.r.epi[d][0], sm.r.epi[d+128][0]);
        u64 o23 = add2(sm.r.epi[d][1], sm.r.epi[d+128][1]);
        float o0, o1, o2, o3;
        upk2(o01, o0, o1); upk2(o23, o2, o3);
        float tval = tcb[d];
        #pragma unroll
        for (int k = 0; k < 4; k++) {
            tval += g_hpro[(k*48 + sIdxH[k])*Dcst + d];
            tval += g_wpro[(k*7  + sIdxW[k])*Dcst + d];
        }
        long ob  = ((long)(n*192 + tp*4))*Dcst + d;
        long obh = OUTHALF + ob;
        out[obh] = tval; out[obh+128] = tval; out[obh+256] = tval; out[obh+384] = tval;
        float base = tval + b2[d];
        out[ob]     = o0 + base;
        out[ob+128] = o1 + base;
        out[ob+256] = o2 + base;
        out[ob+384] = o3 + base;
    }
}

// ---------------- launch ----------------
extern "C" void kernel_launch(void* const* d_in, const int* in_sizes, int n_in,
                              void* d_out, int out_size) {
    const float* x    = (const float*)d_in[0];
    const void*  xm   = d_in[1];
    const void*  ed   = d_in[2];
    const void*  ns   = d_in[3];
    const float* hemb = (const float*)d_in[4];
    const float* wemb = (const float*)d_in[5];
    const float* tcw  = (const float*)d_in[6];
    const float* tcb  = (const float*)d_in[7];
    const float* tvw  = (const float*)d_in[8];
    const float* tvb  = (const float*)d_in[9];
    const float* W1   = (const float*)d_in[10];
    const float* b1   = (const float*)d_in[11];
    const float* W2   = (const float*)d_in[12];
    const float* b2   = (const float*)d_in[13];
    float* out = (float*)d_out;

    k1<<<60, 512>>>(ed, ns, tcw, hemb, wemb, tvw, tvb, W1);
    k2<<<35, 512>>>(ed);
    k3<<<NBcst, 256>>>(xm, x, tcb, b1, W2, b2, out);
}